// round 9
// baseline (speedup 1.0000x reference)
#include <cuda_runtime.h>

#define Bc 8
#define Sc 1048576
#define Cc 4
#define GW 4
#define GH 4
#define NP 16
#define PW 128
#define PH 128

#define CH 2048                 // events per chunk (one block)
#define CPB (Sc/CH)             // 512 chunks per batch
#define PRE 72                  // prefix chunks counted+scattered (11-sigma sat margin)
#define FULL 0xffffffffu

#define FLAG_AGG  0x40000000u
#define FLAG_PRE  0x80000000u
#define FLAG_MASK 0xC0000000u
#define VAL_MASK  0x3FFFFFFFu

// Scratch (zero-init; self-resetting each call for graph replay)
__device__ unsigned g_state[Bc * PRE * NP];
__device__ unsigned g_tick[Bc];

__device__ __forceinline__ int patch_of(float x, float y) {
    int px = min(GW - 1, ((int)x) >> 7);     // coords are non-negative integer-valued
    int py = min(GH - 1, ((int)y) >> 7);
    return (py << 2) | px;
}

__device__ __forceinline__ unsigned sel_mask(int G, unsigned b0, unsigned b1,
                                             unsigned b2, unsigned b3) {
    unsigned m = (G & 1) ? b0 : ~b0;
    m &= (G & 2) ? b1 : ~b1;
    m &= (G & 4) ? b2 : ~b2;
    m &= (G & 8) ? b3 : ~b3;
    return m;
}

// One kernel: count -> publish -> lookback -> scatter -> (last ticket: fallback+reset)
__global__ void __launch_bounds__(256)
fused_main(const float4* __restrict__ ev, float4* __restrict__ outEv,
           float* __restrict__ outMask, int L) {
    int b = blockIdx.x / PRE, c = blockIdx.x % PRE;
    int tid = threadIdx.x, lane = tid & 31, w = tid >> 5;

    __shared__ unsigned wc[8][NP], acc[NP], exc[NP];
    __shared__ unsigned sh[16][NP], accum_s[NP];
    __shared__ int npos_s[NP], done_s[NP], status_s, anyopen, amLast;
    __shared__ unsigned run[NP];

    if (tid < NP) acc[tid] = 0;
    __syncthreads();

    // ---- Phase A: load 256 events/warp into registers, count via ballots ----
    long base = (long)b * Sc + (long)c * CH + w * 256;
    float4 v[8];
#pragma unroll
    for (int j = 0; j < 8; j++) v[j] = ev[base + j * 32 + lane];

    int own = lane & 15;
    unsigned gpack = 0, wcnt = 0;
#pragma unroll
    for (int j = 0; j < 8; j++) {
        int g = patch_of(v[j].x, v[j].y);
        gpack |= (unsigned)g << (4 * j);
        unsigned b0 = __ballot_sync(FULL, g & 1);
        unsigned b1 = __ballot_sync(FULL, g & 2);
        unsigned b2 = __ballot_sync(FULL, g & 4);
        unsigned b3 = __ballot_sync(FULL, g & 8);
        wcnt += (unsigned)__popc(sel_mask(own, b0, b1, b2, b3));
    }
    if (lane < NP) {
        wc[w][lane] = wcnt;
        atomicAdd(&acc[lane], wcnt);
    }
    __syncthreads();

    // ---- Publish aggregate (chunk 0 publishes PREFIX directly) ----
    if (tid < NP) {
        unsigned word = acc[tid] | (c == 0 ? FLAG_PRE : FLAG_AGG);
        *(volatile unsigned*)&g_state[(b * PRE + c) * NP + tid] = word;
    }

    // ---- Decoupled lookback (windowed, 16 chunks x 16 groups per round) ----
    if (c == 0) {
        if (tid < NP) exc[tid] = 0;
        __syncthreads();
    } else {
        if (tid < NP) { npos_s[tid] = c - 1; accum_s[tid] = 0; done_s[tid] = 0; }
        __syncthreads();
        int winbase = c - 1;
        for (;;) {
            int d = tid >> 4, g = tid & 15;
            int pos = winbase - d;
            unsigned wd = 0;
            if (pos >= 0)
                wd = *(volatile unsigned*)&g_state[(b * PRE + pos) * NP + g];
            sh[d][g] = wd;
            __syncthreads();
            if (tid < NP && !done_s[tid]) {
                int np_ = npos_s[tid];
                unsigned a2 = accum_s[tid];
                while (np_ >= winbase - 15 && np_ >= 0) {
                    unsigned wd2 = sh[winbase - np_][tid];
                    unsigned f = wd2 & FLAG_MASK;
                    if (f == 0) break;                   // not yet valid: re-poll
                    a2 += wd2 & VAL_MASK;
                    if (f == FLAG_PRE) { done_s[tid] = 1; break; }
                    np_--;
                }
                npos_s[tid] = np_; accum_s[tid] = a2;
            }
            __syncthreads();
            if (tid == 0) {
                int alldone = 1, allbelow = 1;
#pragma unroll
                for (int g2 = 0; g2 < NP; g2++)
                    if (!done_s[g2]) {
                        alldone = 0;
                        if (npos_s[g2] >= winbase - 15) allbelow = 0;
                    }
                status_s = alldone ? 2 : (allbelow ? 1 : 0);
            }
            __syncthreads();
            if (status_s == 2) break;
            if (status_s == 1) winbase -= 16;
        }
        if (tid < NP) exc[tid] = accum_s[tid];
        __syncthreads();
        if (tid < NP)                                    // publish inclusive PREFIX
            *(volatile unsigned*)&g_state[(b * PRE + c) * NP + tid] =
                (exc[tid] + acc[tid]) | FLAG_PRE;
    }

    // ---- Completion ticket (before scatter; read-side of g_state is done) ----
    if (tid == 0) {
        __threadfence();
        unsigned t = atomicAdd(&g_tick[b], 1u);
        amLast = (t == PRE - 1);
        anyopen = 0;
    }
    __syncthreads();
    if (tid < NP && exc[tid] < (unsigned)L) anyopen = 1;
    __syncthreads();

    // ---- Phase B: scatter from registers ----
    if (anyopen) {
        unsigned bb = 0;
        if (lane < NP) {
            bb = exc[lane];
#pragma unroll
            for (int w2 = 0; w2 < 8; w2++)
                if (w2 < w) bb += wc[w2][lane];
        }
        unsigned lt = (1u << lane) - 1u;
        unsigned rw = 0;
        int b16 = b * NP;
#pragma unroll
        for (int j = 0; j < 8; j++) {
            int g = (gpack >> (4 * j)) & 15;
            unsigned b0 = __ballot_sync(FULL, g & 1);
            unsigned b1 = __ballot_sync(FULL, g & 2);
            unsigned b2 = __ballot_sync(FULL, g & 4);
            unsigned b3 = __ballot_sync(FULL, g & 8);
            unsigned m = sel_mask(g, b0, b1, b2, b3);
            unsigned r = (unsigned)__popc(m & lt);
            unsigned bw = __shfl_sync(FULL, bb + rw, g);
            unsigned rank = bw + r;
            if (rank < (unsigned)L) {
                int px = g & 3, py = g >> 2;
                long row = (long)(b16 + g) * L + rank;
                outEv[row] = make_float4(v[j].x - (float)(px * PW),
                                         v[j].y - (float)(py * PH), v[j].z, v[j].w);
                outMask[row] = 1.0f;
            }
            rw += (unsigned)__popc(sel_mask(own, b0, b1, b2, b3));
        }
    }

    // ---- Last-ticket duties: improbable sequential tail + state reset ----
    if (!amLast) return;

    if (tid < NP)
        run[tid] = *(volatile unsigned*)&g_state[(b * PRE + PRE - 1) * NP + tid]
                   & VAL_MASK;
    __syncthreads();

    int sat = 1;
#pragma unroll
    for (int g2 = 0; g2 < NP; g2++)
        if (run[g2] < (unsigned)L) sat = 0;

    if (!sat) {
        // Sequential correctness path over the remaining chunks (11-sigma rare)
        unsigned lt = (1u << lane) - 1u;
        int b16 = b * NP;
        for (int c2 = PRE; c2 < CPB; c2++) {
            long base2 = (long)b * Sc + (long)c2 * CH + w * 256;
            float4 u[8];
#pragma unroll
            for (int j = 0; j < 8; j++) u[j] = ev[base2 + j * 32 + lane];
            unsigned gp2 = 0, wcnt2 = 0;
#pragma unroll
            for (int j = 0; j < 8; j++) {
                int g = patch_of(u[j].x, u[j].y);
                gp2 |= (unsigned)g << (4 * j);
                unsigned b0 = __ballot_sync(FULL, g & 1);
                unsigned b1 = __ballot_sync(FULL, g & 2);
                unsigned b2 = __ballot_sync(FULL, g & 4);
                unsigned b3 = __ballot_sync(FULL, g & 8);
                wcnt2 += (unsigned)__popc(sel_mask(own, b0, b1, b2, b3));
            }
            if (lane < NP) wc[w][lane] = wcnt2;
            __syncthreads();
            unsigned bb2 = 0;
            if (lane < NP) {
                bb2 = run[lane];
#pragma unroll
                for (int w2 = 0; w2 < 8; w2++)
                    if (w2 < w) bb2 += wc[w2][lane];
            }
            unsigned rw2 = 0;
#pragma unroll
            for (int j = 0; j < 8; j++) {
                int g = (gp2 >> (4 * j)) & 15;
                unsigned b0 = __ballot_sync(FULL, g & 1);
                unsigned b1 = __ballot_sync(FULL, g & 2);
                unsigned b2 = __ballot_sync(FULL, g & 4);
                unsigned b3 = __ballot_sync(FULL, g & 8);
                unsigned m = sel_mask(g, b0, b1, b2, b3);
                unsigned r = (unsigned)__popc(m & lt);
                unsigned bw = __shfl_sync(FULL, bb2 + rw2, g);
                unsigned rank = bw + r;
                if (rank < (unsigned)L) {
                    int px = g & 3, py = g >> 2;
                    long row = (long)(b16 + g) * L + rank;
                    outEv[row] = make_float4(u[j].x - (float)(px * PW),
                                             u[j].y - (float)(py * PH), u[j].z, u[j].w);
                    outMask[row] = 1.0f;
                }
                rw2 += (unsigned)__popc(sel_mask(own, b0, b1, b2, b3));
            }
            __syncthreads();
            if (tid < NP) {
                unsigned s = 0;
#pragma unroll
                for (int w2 = 0; w2 < 8; w2++) s += wc[w2][tid];
                run[tid] += s;
            }
            __syncthreads();
        }
        // tail zero-fill for any group still under capacity
        for (int g = 0; g < NP; g++) {
            unsigned t = run[g];
            if (t < (unsigned)L) {
                long rowBase = (long)(b * NP + g) * L;
                for (int r = (int)t + tid; r < L; r += 256) {
                    outEv[rowBase + r] = make_float4(0.f, 0.f, 0.f, 0.f);
                    outMask[rowBase + r] = 0.f;
                }
            }
        }
        __syncthreads();
    }

    // reset lookback state + ticket for the next graph replay
    for (int i = tid; i < PRE * NP; i += 256)
        g_state[b * PRE * NP + i] = 0;
    __syncthreads();
    if (tid == 0) {
        __threadfence();
        g_tick[b] = 0;
    }
}

extern "C" void kernel_launch(void* const* d_in, const int* in_sizes, int n_in,
                              void* d_out, int out_size) {
    const float4* ev = (const float4*)d_in[0];
    float* out = (float*)d_out;

    int L = out_size / (Bc * NP * (Cc + 1));     // 8192
    float4* outEv = (float4*)out;
    float* outMask = out + (long)Bc * NP * L * Cc;

    fused_main<<<Bc * PRE, 256>>>(ev, outEv, outMask, L);
}

// round 10
// speedup vs baseline: 1.0515x; 1.0515x over previous
#include <cuda_runtime.h>

#define Bc 8
#define Sc 1048576
#define Cc 4
#define GW 4
#define GH 4
#define NP 16
#define PW 128
#define PH 128

#define CH 2048                 // events per chunk (one block)
#define CPB (Sc/CH)             // 512 chunks per batch
#define PRE 72                  // prefix chunks counted+scattered (11-sigma margin)
#define FULL 0xffffffffu

#define TAG_MASK 0xE0000000u    // [31]=PRE [30]=AGG [29]=epoch
#define VAL_MASK 0x1FFFFFFFu
#define TAG_AGG  0x40000000u
#define TAG_PRE  0x80000000u

// Scratch: epoch-tagged, never reset (zero-init at load; tag 0 = invalid)
__device__ unsigned g_state[Bc * PRE * NP];
__device__ unsigned g_tick[Bc];      // monotonic; amLast = (t % PRE)==PRE-1
__device__ unsigned g_epoch[Bc];     // flipped by scanner each call

__device__ __forceinline__ int patch_of(float x, float y) {
    int px = min(GW - 1, ((int)x) >> 7);    // coords are non-negative integer-valued
    int py = min(GH - 1, ((int)y) >> 7);
    return (py << 2) | px;
}

__device__ __forceinline__ unsigned sel_mask(int G, unsigned b0, unsigned b1,
                                             unsigned b2, unsigned b3) {
    unsigned m = (G & 1) ? b0 : ~b0;
    m &= (G & 2) ? b1 : ~b1;
    m &= (G & 4) ? b2 : ~b2;
    m &= (G & 8) ? b3 : ~b3;
    return m;
}

// Improbable (11-sigma) sequential tail for an unsaturated batch + tail-fill.
// __noinline__ so its registers don't inflate the hot path.
__device__ __noinline__ void cold_tail(const float4* __restrict__ ev,
                                       float4* __restrict__ outEv,
                                       float* __restrict__ outMask,
                                       int b, int L, unsigned* run) {
    int tid = threadIdx.x, lane = tid & 31, w = tid >> 5;
    __shared__ unsigned wc2[8][NP];
    int own = lane & 15;
    unsigned lt = (1u << lane) - 1u;
    int b16 = b * NP;
    for (int c2 = PRE; c2 < CPB; c2++) {
        long base2 = (long)b * Sc + (long)c2 * CH + w * 256;
        float4 u[8];
#pragma unroll
        for (int j = 0; j < 8; j++) u[j] = ev[base2 + j * 32 + lane];
        unsigned gp2 = 0, wcnt2 = 0;
#pragma unroll
        for (int j = 0; j < 8; j++) {
            int g = patch_of(u[j].x, u[j].y);
            gp2 |= (unsigned)g << (4 * j);
            unsigned b0 = __ballot_sync(FULL, g & 1);
            unsigned b1 = __ballot_sync(FULL, g & 2);
            unsigned b2 = __ballot_sync(FULL, g & 4);
            unsigned b3 = __ballot_sync(FULL, g & 8);
            wcnt2 += (unsigned)__popc(sel_mask(own, b0, b1, b2, b3));
        }
        if (lane < NP) wc2[w][lane] = wcnt2;
        __syncthreads();
        unsigned bb2 = 0;
        if (lane < NP) {
            bb2 = run[lane];
#pragma unroll
            for (int w2 = 0; w2 < 8; w2++)
                if (w2 < w) bb2 += wc2[w2][lane];
        }
        unsigned rw2 = 0;
#pragma unroll
        for (int j = 0; j < 8; j++) {
            int g = (gp2 >> (4 * j)) & 15;
            unsigned b0 = __ballot_sync(FULL, g & 1);
            unsigned b1 = __ballot_sync(FULL, g & 2);
            unsigned b2 = __ballot_sync(FULL, g & 4);
            unsigned b3 = __ballot_sync(FULL, g & 8);
            unsigned m = sel_mask(g, b0, b1, b2, b3);
            unsigned r = (unsigned)__popc(m & lt);
            unsigned bw = __shfl_sync(FULL, bb2 + rw2, g);
            unsigned rank = bw + r;
            if (rank < (unsigned)L) {
                int px = g & 3, py = g >> 2;
                long row = (long)(b16 + g) * L + rank;
                outEv[row] = make_float4(u[j].x - (float)(px * PW),
                                         u[j].y - (float)(py * PH), u[j].z, u[j].w);
                outMask[row] = 1.0f;
            }
            rw2 += (unsigned)__popc(sel_mask(own, b0, b1, b2, b3));
        }
        __syncthreads();
        if (tid < NP) {
            unsigned s = 0;
#pragma unroll
            for (int w2 = 0; w2 < 8; w2++) s += wc2[w2][tid];
            run[tid] += s;
        }
        __syncthreads();
    }
    for (int g = 0; g < NP; g++) {
        unsigned t = run[g];
        if (t < (unsigned)L) {
            long rowBase = (long)(b * NP + g) * L;
            for (int r = (int)t + tid; r < L; r += 256) {
                outEv[rowBase + r] = make_float4(0.f, 0.f, 0.f, 0.f);
                outMask[rowBase + r] = 0.f;
            }
        }
    }
}

__global__ void __launch_bounds__(256, 4)
fused_main(const float4* __restrict__ ev, float4* __restrict__ outEv,
           float* __restrict__ outMask, int L) {
    int b = blockIdx.x / PRE, c = blockIdx.x % PRE;
    int tid = threadIdx.x, lane = tid & 31, w = tid >> 5;

    __shared__ unsigned acc[NP], wc[8][NP], exc[NP], run[NP];
    __shared__ unsigned sc[PRE * NP];            // scanner workspace (4.6 KB)
    __shared__ int amLast_s, anyopen_s;

    unsigned e = (*(volatile unsigned*)&g_epoch[b]) & 1u;
    unsigned tagA = TAG_AGG | (e << 29);
    unsigned tagP = TAG_PRE | (e << 29);

    if (tid < NP) acc[tid] = 0;
    __syncthreads();

    // ---- Phase A: xy-only read, count via ballots (no float4 held) ----
    const float4* evb = ev + (long)b * Sc + (long)c * CH;
    int idx0 = w * 256 + lane;
    int own = lane & 15;
    unsigned gpack = 0, wcnt = 0;
#pragma unroll
    for (int j = 0; j < 8; j++) {
        float2 p = *(const float2*)(evb + idx0 + j * 32);   // x,y only
        int g = patch_of(p.x, p.y);
        gpack |= (unsigned)g << (4 * j);
        unsigned b0 = __ballot_sync(FULL, g & 1);
        unsigned b1 = __ballot_sync(FULL, g & 2);
        unsigned b2 = __ballot_sync(FULL, g & 4);
        unsigned b3 = __ballot_sync(FULL, g & 8);
        wcnt += (unsigned)__popc(sel_mask(own, b0, b1, b2, b3));
    }
    if (lane < NP) {
        wc[w][lane] = wcnt;
        atomicAdd(&acc[lane], wcnt);
    }
    __syncthreads();

    // ---- Publish AGG + ticket ----
    if (tid < NP)
        *(volatile unsigned*)&g_state[(b * PRE + c) * NP + tid] = acc[tid] | tagA;
    if (tid == 0) {
        __threadfence();
        unsigned t = atomicAdd(&g_tick[b], 1u);
        amLast_s = ((t % PRE) == PRE - 1);
    }
    __syncthreads();
    bool amLast = amLast_s;

    if (amLast) {
        // ---- Scanner: all AGGs are published; scan and broadcast prefixes ----
        __threadfence();
        for (int i = tid; i < PRE * NP; i += 256)
            sc[i] = (*(volatile unsigned*)&g_state[b * PRE * NP + i]) & VAL_MASK;
        __syncthreads();
        if (tid < NP) {
            unsigned s = 0;
#pragma unroll 1
            for (int p = 0; p < PRE; p++) { s += sc[p * NP + tid]; sc[p * NP + tid] = s; }
            run[tid] = s;                               // batch prefix totals
            exc[tid] = sc[c * NP + tid] - acc[tid];     // own exclusive prefix
        }
        __syncthreads();
        for (int i = tid; i < PRE * NP; i += 256)
            *(volatile unsigned*)&g_state[b * PRE * NP + i] = sc[i] | tagP;
    } else {
        // ---- Wait for own PREFIX (fast) or walk AGGs backward (safe) ----
        if (tid < NP) {
            unsigned idx = (b * PRE + c) * NP + tid;
            unsigned wd = 0; int got = 0;
            for (int it = 0; it < 256; it++) {
                wd = *(volatile unsigned*)&g_state[idx];
                if ((wd & TAG_MASK) == tagP) { got = 1; break; }
            }
            unsigned ex;
            if (got) ex = (wd & VAL_MASK) - acc[tid];
            else {
                ex = 0;
                int p = c - 1;
                while (p >= 0) {
                    unsigned w2 = *(volatile unsigned*)&g_state[(b * PRE + p) * NP + tid];
                    unsigned tg = w2 & TAG_MASK;
                    if (tg == tagP) { ex += w2 & VAL_MASK; break; }
                    if (tg == tagA) { ex += w2 & VAL_MASK; p--; }
                    // else: not yet published this epoch — re-poll
                }
            }
            exc[tid] = ex;
        }
        __syncthreads();
    }

    if (tid == 0) anyopen_s = 0;
    __syncthreads();
    if (tid < NP && exc[tid] < (unsigned)L) anyopen_s = 1;
    __syncthreads();

    // ---- Phase B: re-read float4 (L1 hit) and scatter ----
    if (anyopen_s) {
        unsigned bb = 0;
        if (lane < NP) {
            bb = exc[lane];
#pragma unroll
            for (int w2 = 0; w2 < 8; w2++)
                if (w2 < w) bb += wc[w2][lane];
        }
        unsigned lt = (1u << lane) - 1u;
        unsigned rw = 0;
        int b16 = b * NP;
#pragma unroll
        for (int j = 0; j < 8; j++) {
            float4 v = evb[idx0 + j * 32];
            int g = (gpack >> (4 * j)) & 15;
            unsigned b0 = __ballot_sync(FULL, g & 1);
            unsigned b1 = __ballot_sync(FULL, g & 2);
            unsigned b2 = __ballot_sync(FULL, g & 4);
            unsigned b3 = __ballot_sync(FULL, g & 8);
            unsigned m = sel_mask(g, b0, b1, b2, b3);
            unsigned r = (unsigned)__popc(m & lt);
            unsigned bw = __shfl_sync(FULL, bb + rw, g);
            unsigned rank = bw + r;
            if (rank < (unsigned)L) {
                int px = g & 3, py = g >> 2;
                long row = (long)(b16 + g) * L + rank;
                outEv[row] = make_float4(v.x - (float)(px * PW),
                                         v.y - (float)(py * PH), v.z, v.w);
                outMask[row] = 1.0f;
            }
            rw += (unsigned)__popc(sel_mask(own, b0, b1, b2, b3));
        }
    }

    // ---- Scanner epilogue: improbable cold path + epoch flip ----
    if (!amLast) return;

    int sat = 1;
#pragma unroll
    for (int g2 = 0; g2 < NP; g2++)
        if (run[g2] < (unsigned)L) sat = 0;
    if (!sat)
        cold_tail(ev, outEv, outMask, b, L, run);
    __syncthreads();
    if (tid == 0) {
        __threadfence();
        *(volatile unsigned*)&g_epoch[b] = e ^ 1u;
    }
}

extern "C" void kernel_launch(void* const* d_in, const int* in_sizes, int n_in,
                              void* d_out, int out_size) {
    const float4* ev = (const float4*)d_in[0];
    float* out = (float*)d_out;

    int L = out_size / (Bc * NP * (Cc + 1));     // 8192
    float4* outEv = (float4*)out;
    float* outMask = out + (long)Bc * NP * L * Cc;

    fused_main<<<Bc * PRE, 256>>>(ev, outEv, outMask, L);
}

// round 11
// speedup vs baseline: 1.0698x; 1.0175x over previous
#include <cuda_runtime.h>

#define Bc 8
#define Sc 1048576
#define Cc 4
#define GW 4
#define GH 4
#define NP 16
#define PW 128
#define PH 128

#define CH 2048                 // events per chunk (one block)
#define CPB (Sc/CH)             // 512 chunks per batch
#define PRE 72                  // prefix chunks counted+scattered (11-sigma margin)
#define FULL 0xffffffffu

#define TAG_MASK 0xE0000000u    // [31]=PRE [30]=AGG [29]=epoch
#define VAL_MASK 0x1FFFFFFFu
#define TAG_AGG  0x40000000u
#define TAG_PRE  0x80000000u

// Scratch: epoch-tagged, never reset (zero-init at load; tag 0 = invalid)
__device__ unsigned g_state[Bc * PRE * NP];
__device__ unsigned g_tick[Bc];      // monotonic; amLast = (t % PRE)==PRE-1
__device__ unsigned g_epoch[Bc];     // flipped by last-ticket block each call

__device__ __forceinline__ int patch_of(float x, float y) {
    int px = min(GW - 1, ((int)x) >> 7);    // coords are non-negative integer-valued
    int py = min(GH - 1, ((int)y) >> 7);
    return (py << 2) | px;
}

__device__ __forceinline__ unsigned sel_mask(int G, unsigned b0, unsigned b1,
                                             unsigned b2, unsigned b3) {
    unsigned m = (G & 1) ? b0 : ~b0;
    m &= (G & 2) ? b1 : ~b1;
    m &= (G & 4) ? b2 : ~b2;
    m &= (G & 8) ? b3 : ~b3;
    return m;
}

// Improbable (11-sigma) sequential tail for an unsaturated batch + tail-fill.
__device__ __noinline__ void cold_tail(const float4* __restrict__ ev,
                                       float4* __restrict__ outEv,
                                       float* __restrict__ outMask,
                                       int b, int L, unsigned* run) {
    int tid = threadIdx.x, lane = tid & 31, w = tid >> 5;
    __shared__ unsigned wc2[8][NP];
    int own = lane & 15;
    unsigned lt = (1u << lane) - 1u;
    int b16 = b * NP;
    for (int c2 = PRE; c2 < CPB; c2++) {
        long base2 = (long)b * Sc + (long)c2 * CH + w * 256;
        float4 u[8];
#pragma unroll
        for (int j = 0; j < 8; j++) u[j] = ev[base2 + j * 32 + lane];
        unsigned gp2 = 0, wcnt2 = 0;
#pragma unroll
        for (int j = 0; j < 8; j++) {
            int g = patch_of(u[j].x, u[j].y);
            gp2 |= (unsigned)g << (4 * j);
            unsigned b0 = __ballot_sync(FULL, g & 1);
            unsigned b1 = __ballot_sync(FULL, g & 2);
            unsigned b2 = __ballot_sync(FULL, g & 4);
            unsigned b3 = __ballot_sync(FULL, g & 8);
            wcnt2 += (unsigned)__popc(sel_mask(own, b0, b1, b2, b3));
        }
        if (lane < NP) wc2[w][lane] = wcnt2;
        __syncthreads();
        unsigned bb2 = 0;
        if (lane < NP) {
            bb2 = run[lane];
#pragma unroll
            for (int w2 = 0; w2 < 8; w2++)
                if (w2 < w) bb2 += wc2[w2][lane];
        }
        unsigned rw2 = 0;
#pragma unroll
        for (int j = 0; j < 8; j++) {
            int g = (gp2 >> (4 * j)) & 15;
            unsigned b0 = __ballot_sync(FULL, g & 1);
            unsigned b1 = __ballot_sync(FULL, g & 2);
            unsigned b2 = __ballot_sync(FULL, g & 4);
            unsigned b3 = __ballot_sync(FULL, g & 8);
            unsigned m = sel_mask(g, b0, b1, b2, b3);
            unsigned r = (unsigned)__popc(m & lt);
            unsigned bw = __shfl_sync(FULL, bb2 + rw2, g);
            unsigned rank = bw + r;
            if (rank < (unsigned)L) {
                int px = g & 3, py = g >> 2;
                long row = (long)(b16 + g) * L + rank;
                outEv[row] = make_float4(u[j].x - (float)(px * PW),
                                         u[j].y - (float)(py * PH), u[j].z, u[j].w);
                outMask[row] = 1.0f;
            }
            rw2 += (unsigned)__popc(sel_mask(own, b0, b1, b2, b3));
        }
        __syncthreads();
        if (tid < NP) {
            unsigned s = 0;
#pragma unroll
            for (int w2 = 0; w2 < 8; w2++) s += wc2[w2][tid];
            run[tid] += s;
        }
        __syncthreads();
    }
    for (int g = 0; g < NP; g++) {
        unsigned t = run[g];
        if (t < (unsigned)L) {
            long rowBase = (long)(b * NP + g) * L;
            for (int r = (int)t + tid; r < L; r += 256) {
                outEv[rowBase + r] = make_float4(0.f, 0.f, 0.f, 0.f);
                outMask[rowBase + r] = 0.f;
            }
        }
    }
}

__global__ void __launch_bounds__(256, 4)
fused_main(const float4* __restrict__ ev, float4* __restrict__ outEv,
           float* __restrict__ outMask, int L) {
    int b = blockIdx.x / PRE, c = blockIdx.x % PRE;
    int tid = threadIdx.x, lane = tid & 31, w = tid >> 5;

    __shared__ unsigned acc[NP], wc[8][NP], exc[NP], run[NP];
    __shared__ unsigned sh[16][NP], accum_s[NP];
    __shared__ int npos_s[NP], done_s[NP], status_s, amLast_s, anyopen_s;

    unsigned e = (*(volatile unsigned*)&g_epoch[b]) & 1u;
    unsigned tagA = TAG_AGG | (e << 29);
    unsigned tagP = TAG_PRE | (e << 29);

    if (tid < NP) acc[tid] = 0;
    __syncthreads();

    // ---- Phase A: xy-only read; count + per-event warp-local offsets ----
    const float4* evb = ev + (long)b * Sc + (long)c * CH;
    int idx0 = w * 256 + lane;
    int own = lane & 15;

    float2 p[8];
#pragma unroll
    for (int j = 0; j < 8; j++)
        p[j] = *(const float2*)(evb + idx0 + j * 32);   // x,y only; full MLP

    unsigned lt = (1u << lane) - 1u;
    unsigned gpack = 0;
    unsigned long long offpack = 0ull;
    unsigned rw = 0;                                     // lanes' own-group counter
#pragma unroll
    for (int j = 0; j < 8; j++) {
        int g = patch_of(p[j].x, p[j].y);
        gpack |= (unsigned)g << (4 * j);
        unsigned b0 = __ballot_sync(FULL, g & 1);
        unsigned b1 = __ballot_sync(FULL, g & 2);
        unsigned b2 = __ballot_sync(FULL, g & 4);
        unsigned b3 = __ballot_sync(FULL, g & 8);
        unsigned m = sel_mask(g, b0, b1, b2, b3);
        unsigned r = (unsigned)__popc(m & lt);
        unsigned off = __shfl_sync(FULL, rw, g) + r;     // warp-local stable offset
        offpack |= (unsigned long long)(off & 0xffu) << (8 * j);
        rw += (unsigned)__popc(sel_mask(own, b0, b1, b2, b3));
    }
    if (lane < NP) {
        wc[w][lane] = rw;
        atomicAdd(&acc[lane], rw);
    }
    __syncthreads();

    // ---- Publish AGG (chunk 0 publishes PREFIX directly) ----
    if (tid < NP)
        *(volatile unsigned*)&g_state[(b * PRE + c) * NP + tid] =
            acc[tid] | (c == 0 ? tagP : tagA);

    // ---- Windowed decoupled lookback ----
    if (c == 0) {
        if (tid < NP) exc[tid] = 0;
        __syncthreads();
    } else {
        if (tid < NP) { npos_s[tid] = c - 1; accum_s[tid] = 0; done_s[tid] = 0; }
        __syncthreads();
        int winbase = c - 1;
        for (;;) {
            int d = tid >> 4, g = tid & 15;
            int pos = winbase - d;
            unsigned wd = 0;
            if (pos >= 0)
                wd = *(volatile unsigned*)&g_state[(b * PRE + pos) * NP + g];
            sh[d][g] = wd;
            __syncthreads();
            if (tid < NP && !done_s[tid]) {
                int np_ = npos_s[tid];
                unsigned a2 = accum_s[tid];
                while (np_ >= winbase - 15 && np_ >= 0) {
                    unsigned wd2 = sh[winbase - np_][tid];
                    unsigned tg = wd2 & TAG_MASK;
                    if (tg == tagP) { a2 += wd2 & VAL_MASK; done_s[tid] = 1; break; }
                    if (tg != tagA) break;               // stale/unpublished: re-poll
                    a2 += wd2 & VAL_MASK;
                    np_--;
                }
                npos_s[tid] = np_; accum_s[tid] = a2;
            }
            __syncthreads();
            if (tid == 0) {
                int alldone = 1, allbelow = 1;
#pragma unroll
                for (int g2 = 0; g2 < NP; g2++)
                    if (!done_s[g2]) {
                        alldone = 0;
                        if (npos_s[g2] >= winbase - 15) allbelow = 0;
                    }
                status_s = alldone ? 2 : (allbelow ? 1 : 0);
            }
            __syncthreads();
            if (status_s == 2) break;
            if (status_s == 1) winbase -= 16;
        }
        if (tid < NP) exc[tid] = accum_s[tid];
        __syncthreads();
        if (tid < NP)                                    // publish inclusive PREFIX
            *(volatile unsigned*)&g_state[(b * PRE + c) * NP + tid] =
                (exc[tid] + acc[tid]) | tagP;
    }

    // ---- Ticket (after own PREFIX publish; no g_state reads after this) ----
    if (tid == 0) {
        __threadfence();
        unsigned t = atomicAdd(&g_tick[b], 1u);
        amLast_s = ((t % PRE) == PRE - 1);
        anyopen_s = 0;
    }
    __syncthreads();
    if (tid < NP && exc[tid] < (unsigned)L) anyopen_s = 1;
    __syncthreads();

    // ---- Phase B: re-read float4 (L1 hit), rank = base + precomputed offset ----
    if (anyopen_s) {
        unsigned bb = 0;
        if (lane < NP) {
            bb = exc[lane];
#pragma unroll
            for (int w2 = 0; w2 < 8; w2++)
                if (w2 < w) bb += wc[w2][lane];
        }
        int b16 = b * NP;
#pragma unroll
        for (int j = 0; j < 8; j++) {
            int g = (gpack >> (4 * j)) & 15;
            unsigned bw = __shfl_sync(FULL, bb, g);
            unsigned rank = bw + (unsigned)((offpack >> (8 * j)) & 0xffu);
            if (rank < (unsigned)L) {
                float4 v = evb[idx0 + j * 32];
                int px = g & 3, py = g >> 2;
                long row = (long)(b16 + g) * L + rank;
                outEv[row] = make_float4(v.x - (float)(px * PW),
                                         v.y - (float)(py * PH), v.z, v.w);
                outMask[row] = 1.0f;
            }
        }
    }

    // ---- Last-ticket duties: improbable cold path + epoch flip ----
    if (!amLast_s) return;

    if (tid < NP)
        run[tid] = (*(volatile unsigned*)&g_state[(b * PRE + PRE - 1) * NP + tid])
                   & VAL_MASK;
    __syncthreads();

    int sat = 1;
#pragma unroll
    for (int g2 = 0; g2 < NP; g2++)
        if (run[g2] < (unsigned)L) sat = 0;
    if (!sat)
        cold_tail(ev, outEv, outMask, b, L, run);
    __syncthreads();
    if (tid == 0) {
        __threadfence();
        *(volatile unsigned*)&g_epoch[b] = e ^ 1u;
    }
}

extern "C" void kernel_launch(void* const* d_in, const int* in_sizes, int n_in,
                              void* d_out, int out_size) {
    const float4* ev = (const float4*)d_in[0];
    float* out = (float*)d_out;

    int L = out_size / (Bc * NP * (Cc + 1));     // 8192
    float4* outEv = (float4*)out;
    float* outMask = out + (long)Bc * NP * L * Cc;

    fused_main<<<Bc * PRE, 256>>>(ev, outEv, outMask, L);
}

// round 12
// speedup vs baseline: 1.1521x; 1.0769x over previous
#include <cuda_runtime.h>

#define Bc 8
#define Sc 1048576
#define Cc 4
#define GW 4
#define GH 4
#define NP 16
#define PW 128
#define PH 128

#define CH 2048                 // events per chunk (one block)
#define CPB (Sc/CH)             // 512 chunks per batch
#define PRE 72                  // prefix chunks counted+scattered (11-sigma margin)
#define FULL 0xffffffffu

#define TAG_MASK 0xE0000000u    // [31]=PRE [30]=AGG [29]=epoch
#define VAL_MASK 0x1FFFFFFFu
#define TAG_AGG  0x40000000u
#define TAG_PRE  0x80000000u

// Scratch: epoch-tagged, never reset (zero-init at load; tag 0 = invalid)
__device__ unsigned g_state[Bc * PRE * NP];
__device__ unsigned g_tick[Bc];      // monotonic; amLast = (t % PRE)==PRE-1
__device__ unsigned g_epoch[Bc];     // flipped by last-ticket block each call

__device__ __forceinline__ int patch_of(float x, float y) {
    int px = min(GW - 1, ((int)x) >> 7);    // coords are non-negative integer-valued
    int py = min(GH - 1, ((int)y) >> 7);
    return (py << 2) | px;
}

__device__ __forceinline__ unsigned sel_mask(int G, unsigned b0, unsigned b1,
                                             unsigned b2, unsigned b3) {
    unsigned m = (G & 1) ? b0 : ~b0;
    m &= (G & 2) ? b1 : ~b1;
    m &= (G & 4) ? b2 : ~b2;
    m &= (G & 8) ? b3 : ~b3;
    return m;
}

// Improbable (11-sigma) sequential tail for an unsaturated batch + tail-fill.
__device__ __noinline__ void cold_tail(const float4* __restrict__ ev,
                                       float4* __restrict__ outEv,
                                       float* __restrict__ outMask,
                                       int b, int L, unsigned* run) {
    int tid = threadIdx.x, lane = tid & 31, w = tid >> 5;
    __shared__ unsigned wc2[8][NP];
    int own = lane & 15;
    unsigned lt = (1u << lane) - 1u;
    int b16 = b * NP;
    for (int c2 = PRE; c2 < CPB; c2++) {
        long base2 = (long)b * Sc + (long)c2 * CH + w * 256;
        float4 u[8];
#pragma unroll
        for (int j = 0; j < 8; j++) u[j] = ev[base2 + j * 32 + lane];
        unsigned gp2 = 0, wcnt2 = 0;
#pragma unroll
        for (int j = 0; j < 8; j++) {
            int g = patch_of(u[j].x, u[j].y);
            gp2 |= (unsigned)g << (4 * j);
            unsigned b0 = __ballot_sync(FULL, g & 1);
            unsigned b1 = __ballot_sync(FULL, g & 2);
            unsigned b2 = __ballot_sync(FULL, g & 4);
            unsigned b3 = __ballot_sync(FULL, g & 8);
            wcnt2 += (unsigned)__popc(sel_mask(own, b0, b1, b2, b3));
        }
        if (lane < NP) wc2[w][lane] = wcnt2;
        __syncthreads();
        unsigned bb2 = 0;
        if (lane < NP) {
            bb2 = run[lane];
#pragma unroll
            for (int w2 = 0; w2 < 8; w2++)
                if (w2 < w) bb2 += wc2[w2][lane];
        }
        unsigned rw2 = 0;
#pragma unroll
        for (int j = 0; j < 8; j++) {
            int g = (gp2 >> (4 * j)) & 15;
            unsigned b0 = __ballot_sync(FULL, g & 1);
            unsigned b1 = __ballot_sync(FULL, g & 2);
            unsigned b2 = __ballot_sync(FULL, g & 4);
            unsigned b3 = __ballot_sync(FULL, g & 8);
            unsigned m = sel_mask(g, b0, b1, b2, b3);
            unsigned r = (unsigned)__popc(m & lt);
            unsigned bw = __shfl_sync(FULL, bb2 + rw2, g);
            unsigned rank = bw + r;
            if (rank < (unsigned)L) {
                int px = g & 3, py = g >> 2;
                long row = (long)(b16 + g) * L + rank;
                outEv[row] = make_float4(u[j].x - (float)(px * PW),
                                         u[j].y - (float)(py * PH), u[j].z, u[j].w);
                outMask[row] = 1.0f;
            }
            rw2 += (unsigned)__popc(sel_mask(own, b0, b1, b2, b3));
        }
        __syncthreads();
        if (tid < NP) {
            unsigned s = 0;
#pragma unroll
            for (int w2 = 0; w2 < 8; w2++) s += wc2[w2][tid];
            run[tid] += s;
        }
        __syncthreads();
    }
    for (int g = 0; g < NP; g++) {
        unsigned t = run[g];
        if (t < (unsigned)L) {
            long rowBase = (long)(b * NP + g) * L;
            for (int r = (int)t + tid; r < L; r += 256) {
                outEv[rowBase + r] = make_float4(0.f, 0.f, 0.f, 0.f);
                outMask[rowBase + r] = 0.f;
            }
        }
    }
}

__global__ void __launch_bounds__(256, 4)
fused_main(const float4* __restrict__ ev, float4* __restrict__ outEv,
           float* __restrict__ outMask, int L) {
    int b = blockIdx.x / PRE, c = blockIdx.x % PRE;
    int tid = threadIdx.x, lane = tid & 31, w = tid >> 5;

    __shared__ unsigned acc[NP], wc[8][NP], exc[NP], run[NP];
    __shared__ unsigned sh[16][NP], accum_s[NP];
    __shared__ int npos_s[NP], done_s[NP], status_s, amLast_s, anyopen_s;

    unsigned e = (*(volatile unsigned*)&g_epoch[b]) & 1u;
    unsigned tagA = TAG_AGG | (e << 29);
    unsigned tagP = TAG_PRE | (e << 29);

    if (tid < NP) acc[tid] = 0;
    __syncthreads();

    // ---- Phase A: xy-only read; count + per-event warp-local offsets ----
    const float4* evb = ev + (long)b * Sc + (long)c * CH;
    int idx0 = w * 256 + lane;
    int own = lane & 15;

    float2 p[8];
#pragma unroll
    for (int j = 0; j < 8; j++)
        p[j] = *(const float2*)(evb + idx0 + j * 32);   // x,y only; full MLP

    unsigned lt = (1u << lane) - 1u;
    unsigned gpack = 0;
    unsigned long long offpack = 0ull;
    unsigned rw = 0;                                     // lanes' own-group counter
#pragma unroll
    for (int j = 0; j < 8; j++) {
        int g = patch_of(p[j].x, p[j].y);
        gpack |= (unsigned)g << (4 * j);
        unsigned b0 = __ballot_sync(FULL, g & 1);
        unsigned b1 = __ballot_sync(FULL, g & 2);
        unsigned b2 = __ballot_sync(FULL, g & 4);
        unsigned b3 = __ballot_sync(FULL, g & 8);
        unsigned m = sel_mask(g, b0, b1, b2, b3);
        unsigned r = (unsigned)__popc(m & lt);
        unsigned off = __shfl_sync(FULL, rw, g) + r;     // warp-local stable offset
        offpack |= (unsigned long long)(off & 0xffu) << (8 * j);
        rw += (unsigned)__popc(sel_mask(own, b0, b1, b2, b3));
    }
    if (lane < NP) {
        wc[w][lane] = rw;
        atomicAdd(&acc[lane], rw);
    }
    __syncthreads();

    // ---- Publish AGG (chunk 0 publishes PREFIX directly) ----
    if (tid < NP)
        *(volatile unsigned*)&g_state[(b * PRE + c) * NP + tid] =
            acc[tid] | (c == 0 ? tagP : tagA);

    // ---- Windowed decoupled lookback ----
    if (c == 0) {
        if (tid < NP) exc[tid] = 0;
        __syncthreads();
    } else {
        if (tid < NP) { npos_s[tid] = c - 1; accum_s[tid] = 0; done_s[tid] = 0; }
        __syncthreads();
        int winbase = c - 1;
        for (;;) {
            int d = tid >> 4, g = tid & 15;
            int pos = winbase - d;
            unsigned wd = 0;
            if (pos >= 0)
                wd = *(volatile unsigned*)&g_state[(b * PRE + pos) * NP + g];
            sh[d][g] = wd;
            __syncthreads();
            if (tid < NP && !done_s[tid]) {
                int np_ = npos_s[tid];
                unsigned a2 = accum_s[tid];
                while (np_ >= winbase - 15 && np_ >= 0) {
                    unsigned wd2 = sh[winbase - np_][tid];
                    unsigned tg = wd2 & TAG_MASK;
                    if (tg == tagP) { a2 += wd2 & VAL_MASK; done_s[tid] = 1; break; }
                    if (tg != tagA) break;               // stale/unpublished: re-poll
                    a2 += wd2 & VAL_MASK;
                    np_--;
                }
                npos_s[tid] = np_; accum_s[tid] = a2;
            }
            __syncthreads();
            if (tid == 0) {
                int alldone = 1, allbelow = 1;
#pragma unroll
                for (int g2 = 0; g2 < NP; g2++)
                    if (!done_s[g2]) {
                        alldone = 0;
                        if (npos_s[g2] >= winbase - 15) allbelow = 0;
                    }
                status_s = alldone ? 2 : (allbelow ? 1 : 0);
            }
            __syncthreads();
            if (status_s == 2) break;
            if (status_s == 1) winbase -= 16;
        }
        if (tid < NP) exc[tid] = accum_s[tid];
        __syncthreads();
        if (tid < NP)                                    // publish inclusive PREFIX
            *(volatile unsigned*)&g_state[(b * PRE + c) * NP + tid] =
                (exc[tid] + acc[tid]) | tagP;
    }

    // ---- Ticket: NO fence. amLast correctness is poll-based below. ----
    if (tid == 0) {
        unsigned t = atomicAdd(&g_tick[b], 1u);
        amLast_s = ((t % PRE) == PRE - 1);
        anyopen_s = 0;
    }
    __syncthreads();
    if (tid < NP && exc[tid] < (unsigned)L) anyopen_s = 1;
    __syncthreads();

    // ---- Phase B: re-read float4 (L1 hit), rank = base + precomputed offset ----
    if (anyopen_s) {
        unsigned bb = 0;
        if (lane < NP) {
            bb = exc[lane];
#pragma unroll
            for (int w2 = 0; w2 < 8; w2++)
                if (w2 < w) bb += wc[w2][lane];
        }
        int b16 = b * NP;
#pragma unroll
        for (int j = 0; j < 8; j++) {
            int g = (gpack >> (4 * j)) & 15;
            unsigned bw = __shfl_sync(FULL, bb, g);
            unsigned rank = bw + (unsigned)((offpack >> (8 * j)) & 0xffu);
            if (rank < (unsigned)L) {
                float4 v = evb[idx0 + j * 32];
                int px = g & 3, py = g >> 2;
                long row = (long)(b16 + g) * L + rank;
                outEv[row] = make_float4(v.x - (float)(px * PW),
                                         v.y - (float)(py * PH), v.z, v.w);
                outMask[row] = 1.0f;
            }
        }
    }

    // ---- Last-ticket duties: poll last PREFIX, improbable cold path, epoch flip ----
    if (!amLast_s) return;

    if (tid < NP) {
        // Publisher stored PREFIX before taking its ticket; poll until visible.
        unsigned wd;
        do {
            wd = *(volatile unsigned*)&g_state[(b * PRE + PRE - 1) * NP + tid];
        } while ((wd & TAG_MASK) != tagP);
        run[tid] = wd & VAL_MASK;
    }
    __syncthreads();

    int sat = 1;
#pragma unroll
    for (int g2 = 0; g2 < NP; g2++)
        if (run[g2] < (unsigned)L) sat = 0;
    if (!sat)
        cold_tail(ev, outEv, outMask, b, L, run);
    __syncthreads();
    if (tid == 0)
        *(volatile unsigned*)&g_epoch[b] = e ^ 1u;   // kernel boundary orders replays
}

extern "C" void kernel_launch(void* const* d_in, const int* in_sizes, int n_in,
                              void* d_out, int out_size) {
    const float4* ev = (const float4*)d_in[0];
    float* out = (float*)d_out;

    int L = out_size / (Bc * NP * (Cc + 1));     // 8192
    float4* outEv = (float4*)out;
    float* outMask = out + (long)Bc * NP * L * Cc;

    fused_main<<<Bc * PRE, 256>>>(ev, outEv, outMask, L);
}

// round 13
// speedup vs baseline: 1.2057x; 1.0465x over previous
#include <cuda_runtime.h>

#define Bc 8
#define Sc 1048576
#define Cc 4
#define GW 4
#define GH 4
#define NP 16
#define PW 128
#define PH 128

#define CH 2048                 // events per chunk (one block)
#define CPB (Sc/CH)             // 512 chunks per batch
#define PRE 72                  // prefix chunks counted+scattered (11-sigma margin)
#define FULL 0xffffffffu

#define TAG_MASK 0x60000000u    // [30]=AGG-valid [29]=epoch
#define VAL_MASK 0x1FFFFFFFu
#define TAG_AGG  0x40000000u

// Scratch: epoch-tagged, never reset. Layout: [b][g][chunk] (transposed).
__device__ unsigned g_state[Bc * NP * PRE];
__device__ unsigned g_tick[Bc];      // monotonic; amLast = (t % PRE)==PRE-1
__device__ unsigned g_epoch[Bc];     // flipped by last-ticket block each call

__device__ __forceinline__ int patch_of(float x, float y) {
    int px = min(GW - 1, ((int)x) >> 7);    // coords are non-negative integer-valued
    int py = min(GH - 1, ((int)y) >> 7);
    return (py << 2) | px;
}

__device__ __forceinline__ unsigned sel_mask(int G, unsigned b0, unsigned b1,
                                             unsigned b2, unsigned b3) {
    unsigned m = (G & 1) ? b0 : ~b0;
    m &= (G & 2) ? b1 : ~b1;
    m &= (G & 4) ? b2 : ~b2;
    m &= (G & 8) ? b3 : ~b3;
    return m;
}

// Poll-sum AGGs of chunks [0,n) for groups 2w and 2w+1; result into dst[g].
__device__ __forceinline__ void poll_sum(const unsigned* bstate, int n,
                                         unsigned tagA, int lane, int w,
                                         unsigned* dst) {
#pragma unroll
    for (int half = 0; half < 2; half++) {
        int g = 2 * w + half;
        const unsigned* base = bstate + g * PRE;
        unsigned sum;
        for (;;) {
            sum = 0;
            int ok = 1;
            for (int c0 = 0; c0 < n; c0 += 32) {
                int cc = c0 + lane;
                if (cc < n) {
                    unsigned wd = *(volatile const unsigned*)&base[cc];
                    if ((wd & TAG_MASK) != tagA) ok = 0;
                    sum += wd & VAL_MASK;
                }
            }
            if (__all_sync(FULL, ok)) break;
        }
#pragma unroll
        for (int off = 16; off; off >>= 1)
            sum += __shfl_down_sync(FULL, sum, off);
        if (lane == 0) dst[g] = sum;
    }
}

// Improbable (11-sigma) sequential tail for an unsaturated batch + tail-fill.
__device__ __noinline__ void cold_tail(const float4* __restrict__ ev,
                                       float4* __restrict__ outEv,
                                       float* __restrict__ outMask,
                                       int b, int L, unsigned* run) {
    int tid = threadIdx.x, lane = tid & 31, w = tid >> 5;
    __shared__ unsigned wc2[8][NP];
    int own = lane & 15;
    unsigned lt = (1u << lane) - 1u;
    int b16 = b * NP;
    for (int c2 = PRE; c2 < CPB; c2++) {
        long base2 = (long)b * Sc + (long)c2 * CH + w * 256;
        float4 u[8];
#pragma unroll
        for (int j = 0; j < 8; j++) u[j] = ev[base2 + j * 32 + lane];
        unsigned gp2 = 0, wcnt2 = 0;
#pragma unroll
        for (int j = 0; j < 8; j++) {
            int g = patch_of(u[j].x, u[j].y);
            gp2 |= (unsigned)g << (4 * j);
            unsigned b0 = __ballot_sync(FULL, g & 1);
            unsigned b1 = __ballot_sync(FULL, g & 2);
            unsigned b2 = __ballot_sync(FULL, g & 4);
            unsigned b3 = __ballot_sync(FULL, g & 8);
            wcnt2 += (unsigned)__popc(sel_mask(own, b0, b1, b2, b3));
        }
        if (lane < NP) wc2[w][lane] = wcnt2;
        __syncthreads();
        unsigned bb2 = 0;
        if (lane < NP) {
            bb2 = run[lane];
#pragma unroll
            for (int w2 = 0; w2 < 8; w2++)
                if (w2 < w) bb2 += wc2[w2][lane];
        }
        unsigned rw2 = 0;
#pragma unroll
        for (int j = 0; j < 8; j++) {
            int g = (gp2 >> (4 * j)) & 15;
            unsigned b0 = __ballot_sync(FULL, g & 1);
            unsigned b1 = __ballot_sync(FULL, g & 2);
            unsigned b2 = __ballot_sync(FULL, g & 4);
            unsigned b3 = __ballot_sync(FULL, g & 8);
            unsigned m = sel_mask(g, b0, b1, b2, b3);
            unsigned r = (unsigned)__popc(m & lt);
            unsigned bw = __shfl_sync(FULL, bb2 + rw2, g);
            unsigned rank = bw + r;
            if (rank < (unsigned)L) {
                int px = g & 3, py = g >> 2;
                long row = (long)(b16 + g) * L + rank;
                outEv[row] = make_float4(u[j].x - (float)(px * PW),
                                         u[j].y - (float)(py * PH), u[j].z, u[j].w);
                outMask[row] = 1.0f;
            }
            rw2 += (unsigned)__popc(sel_mask(own, b0, b1, b2, b3));
        }
        __syncthreads();
        if (tid < NP) {
            unsigned s = 0;
#pragma unroll
            for (int w2 = 0; w2 < 8; w2++) s += wc2[w2][tid];
            run[tid] += s;
        }
        __syncthreads();
    }
    for (int g = 0; g < NP; g++) {
        unsigned t = run[g];
        if (t < (unsigned)L) {
            long rowBase = (long)(b * NP + g) * L;
            for (int r = (int)t + tid; r < L; r += 256) {
                outEv[rowBase + r] = make_float4(0.f, 0.f, 0.f, 0.f);
                outMask[rowBase + r] = 0.f;
            }
        }
    }
}

__global__ void __launch_bounds__(256, 4)
fused_main(const float4* __restrict__ ev, float4* __restrict__ outEv,
           float* __restrict__ outMask, int L) {
    int b = blockIdx.x / PRE, c = blockIdx.x % PRE;
    int tid = threadIdx.x, lane = tid & 31, w = tid >> 5;

    __shared__ unsigned wc[8][NP], exc[NP], run[NP];
    __shared__ int amLast_s, anyopen_s;

    unsigned e = (*(volatile unsigned*)&g_epoch[b]) & 1u;
    unsigned tagA = TAG_AGG | (e << 29);
    unsigned* bstate = &g_state[b * NP * PRE];

    // ---- Phase A: xy-only read; count + per-event warp-local offsets ----
    const float4* evb = ev + (long)b * Sc + (long)c * CH;
    int idx0 = w * 256 + lane;
    int own = lane & 15;

    float2 p[8];
#pragma unroll
    for (int j = 0; j < 8; j++)
        p[j] = *(const float2*)(evb + idx0 + j * 32);   // x,y only; full MLP

    unsigned lt = (1u << lane) - 1u;
    unsigned gpack = 0;
    unsigned long long offpack = 0ull;
    unsigned rw = 0;                                     // lanes' own-group counter
#pragma unroll
    for (int j = 0; j < 8; j++) {
        int g = patch_of(p[j].x, p[j].y);
        gpack |= (unsigned)g << (4 * j);
        unsigned b0 = __ballot_sync(FULL, g & 1);
        unsigned b1 = __ballot_sync(FULL, g & 2);
        unsigned b2 = __ballot_sync(FULL, g & 4);
        unsigned b3 = __ballot_sync(FULL, g & 8);
        unsigned m = sel_mask(g, b0, b1, b2, b3);
        unsigned r = (unsigned)__popc(m & lt);
        unsigned off = __shfl_sync(FULL, rw, g) + r;     // warp-local stable offset
        offpack |= (unsigned long long)(off & 0xffu) << (8 * j);
        rw += (unsigned)__popc(sel_mask(own, b0, b1, b2, b3));
    }
    if (lane < NP) wc[w][lane] = rw;
    __syncthreads();

    // ---- Publish AGG (transposed layout) ----
    if (tid < NP) {
        unsigned s = 0;
#pragma unroll
        for (int w2 = 0; w2 < 8; w2++) s += wc[w2][tid];
        *(volatile unsigned*)&bstate[tid * PRE + c] = s | tagA;
    }
    __syncthreads();                         // all 16 publishes issued

    // ---- Ticket (no fence; all later reads are poll-based) ----
    if (tid == 0) {
        unsigned t = atomicAdd(&g_tick[b], 1u);
        amLast_s = ((t % PRE) == PRE - 1);
        anyopen_s = 0;
    }

    // ---- Exclusive prefix: direct poll-sum of predecessor AGGs ----
    if (c == 0) {
        if (tid < NP) exc[tid] = 0;
    } else {
        poll_sum(bstate, c, tagA, lane, w, exc);
    }
    __syncthreads();
    if (tid < NP && exc[tid] < (unsigned)L) anyopen_s = 1;
    __syncthreads();

    // ---- Phase B: re-read float4 (L1 hit), rank = base + precomputed offset ----
    if (anyopen_s) {
        unsigned bb = 0;
        if (lane < NP) {
            bb = exc[lane];
#pragma unroll
            for (int w2 = 0; w2 < 8; w2++)
                if (w2 < w) bb += wc[w2][lane];
        }
        int b16 = b * NP;
#pragma unroll
        for (int j = 0; j < 8; j++) {
            int g = (gpack >> (4 * j)) & 15;
            unsigned bw = __shfl_sync(FULL, bb, g);
            unsigned rank = bw + (unsigned)((offpack >> (8 * j)) & 0xffu);
            if (rank < (unsigned)L) {
                float4 v = evb[idx0 + j * 32];
                int px = g & 3, py = g >> 2;
                long row = (long)(b16 + g) * L + rank;
                outEv[row] = make_float4(v.x - (float)(px * PW),
                                         v.y - (float)(py * PH), v.z, v.w);
                outMask[row] = 1.0f;
            }
        }
    }

    // ---- Last-ticket duties: poll batch totals, improbable cold path, epoch flip ----
    if (!amLast_s) return;

    poll_sum(bstate, PRE, tagA, lane, w, run);
    __syncthreads();

    int sat = 1;
#pragma unroll
    for (int g2 = 0; g2 < NP; g2++)
        if (run[g2] < (unsigned)L) sat = 0;
    if (!sat)
        cold_tail(ev, outEv, outMask, b, L, run);
    __syncthreads();
    if (tid == 0)
        *(volatile unsigned*)&g_epoch[b] = e ^ 1u;   // kernel boundary orders replays
}

extern "C" void kernel_launch(void* const* d_in, const int* in_sizes, int n_in,
                              void* d_out, int out_size) {
    const float4* ev = (const float4*)d_in[0];
    float* out = (float*)d_out;

    int L = out_size / (Bc * NP * (Cc + 1));     // 8192
    float4* outEv = (float4*)out;
    float* outMask = out + (long)Bc * NP * L * Cc;

    fused_main<<<Bc * PRE, 256>>>(ev, outEv, outMask, L);
}